// round 16
// baseline (speedup 1.0000x reference)
#include <cuda_runtime.h>
#include <cstdint>

#define N_FFT   4096
#define THREADS 128

// XOR swizzle in float2-index space: bit1 ^= i8, bit2 ^= i9, bit3 ^= i7^i10.
// Bank-audited: stage-1 stores CF, stage-2 load/store CF, final octet gather 2-way.
__device__ __forceinline__ int SWX(int i) {
    return i ^ (((i >> 8) & 1) << 1) ^ (((i >> 9) & 1) << 2)
             ^ ((((i >> 7) ^ (i >> 10)) & 1) << 3);
}

__device__ __forceinline__ float2 cadd(float2 a, float2 b){ return make_float2(a.x+b.x, a.y+b.y); }
__device__ __forceinline__ float2 csub(float2 a, float2 b){ return make_float2(a.x-b.x, a.y-b.y); }
__device__ __forceinline__ float2 cmul(float2 a, float2 b){
    return make_float2(fmaf(a.x, b.x, -a.y*b.y), fmaf(a.x, b.y, a.y*b.x));
}
__device__ __forceinline__ float2 cmuli(float2 a){ return make_float2(-a.y, a.x); }   // *(+i)

// 8-point DFT core, omega8 = e^{+2*pi*i/8}  (positive-sign DFT)
__device__ __forceinline__ void dft8(const float2 a[8], float2 b[8]) {
    float2 t0 = cadd(a[0], a[4]);
    float2 t1 = csub(a[0], a[4]);
    float2 t2 = cadd(a[2], a[6]);
    float2 t3 = cmuli(csub(a[2], a[6]));
    float2 u0 = cadd(a[1], a[5]);
    float2 u1 = csub(a[1], a[5]);
    float2 u2 = cadd(a[3], a[7]);
    float2 u3 = cmuli(csub(a[3], a[7]));

    float2 E0 = cadd(t0, t2), E2 = csub(t0, t2);
    float2 E1 = cadd(t1, t3), E3 = csub(t1, t3);
    float2 O0 = cadd(u0, u2), O2 = csub(u0, u2);
    float2 O1 = cadd(u1, u3), O3 = csub(u1, u3);

    const float r = 0.7071067811865476f;
    float2 W1 = make_float2(r * (O1.x - O1.y),  r * (O1.x + O1.y));
    float2 W2 = cmuli(O2);
    float2 W3 = make_float2(-r * (O3.x + O3.y), r * (O3.x - O3.y));

    b[0] = cadd(E0, O0); b[4] = csub(E0, O0);
    b[1] = cadd(E1, W1); b[5] = csub(E1, W1);
    b[2] = cadd(E2, W2); b[6] = csub(E2, W2);
    b[3] = cadd(E3, W3); b[7] = csub(E3, W3);
}

// 16-point DFT (positive sign) via two dft8 + omega16^r combine. In place.
__device__ __forceinline__ void dft16(float2 v[16]) {
    float2 e[8], o[8], E[8], O[8];
#pragma unroll
    for (int n = 0; n < 8; n++) { e[n] = v[2*n]; o[n] = v[2*n+1]; }
    dft8(e, E);
    dft8(o, O);
    const float C = 0.9238795325112868f, S = 0.3826834323650898f, R = 0.7071067811865476f;
    float2 T[8];
    T[0] = O[0];
    T[1] = cmul(O[1], make_float2( C,  S));
    T[2] = make_float2(R*(O[2].x - O[2].y),  R*(O[2].x + O[2].y));   // *e^{i pi/4}
    T[3] = cmul(O[3], make_float2( S,  C));
    T[4] = cmuli(O[4]);
    T[5] = cmul(O[5], make_float2(-S,  C));
    T[6] = make_float2(-R*(O[6].x + O[6].y), R*(O[6].x - O[6].y));   // *e^{i 3pi/4}
    T[7] = cmul(O[7], make_float2(-C,  S));
#pragma unroll
    for (int r = 0; r < 8; r++) { v[r] = cadd(E[r], T[r]); v[r+8] = csub(E[r], T[r]); }
}

// v[r] *= w1^r, r=1..15, log-depth power generation.
__device__ __forceinline__ void twiddle16w(float2 v[16], float2 w1) {
    float2 w2  = cmul(w1, w1);   v[1]  = cmul(v[1],  w1);
    float2 w3  = cmul(w2, w1);   v[2]  = cmul(v[2],  w2);
    float2 w4  = cmul(w2, w2);   v[3]  = cmul(v[3],  w3);
    float2 w5  = cmul(w3, w2);   v[4]  = cmul(v[4],  w4);
    float2 w6  = cmul(w3, w3);   v[5]  = cmul(v[5],  w5);
    float2 w7  = cmul(w4, w3);   v[6]  = cmul(v[6],  w6);
    float2 w8  = cmul(w4, w4);   v[7]  = cmul(v[7],  w7);
    float2 w9  = cmul(w5, w4);   v[8]  = cmul(v[8],  w8);
    float2 w10 = cmul(w5, w5);   v[9]  = cmul(v[9],  w9);
    float2 w11 = cmul(w6, w5);   v[10] = cmul(v[10], w10);
    float2 w12 = cmul(w6, w6);   v[11] = cmul(v[11], w11);
    float2 w13 = cmul(w7, w6);   v[12] = cmul(v[12], w12);
    float2 w14 = cmul(w7, w7);   v[13] = cmul(v[13], w13);
    float2 w15 = cmul(w8, w7);   v[14] = cmul(v[14], w14);
                                 v[15] = cmul(v[15], w15);
}

__global__ void __launch_bounds__(THREADS, 8)
idct_fft_kernel(const float* __restrict__ x, float* __restrict__ y) {
    __shared__ float2 buf[2048];       // exact: XOR swizzle is bijective, no padding
    __shared__ float2 lut[15][8];      // stage-2 twiddles e^{2*pi*i*p*r/128}, r=1..15
    const int t = threadIdx.x;
    const size_t rowoff = (size_t)blockIdx.x * N_FFT;
    const float* __restrict__ xr = x + rowoff;

    // ---- fill stage-2 twiddle LUT (ready after the first __syncthreads) ----
    if (t < 120) {
        int r = (t >> 3) + 1, p = t & 7;
        float s, c;
        __sincosf((float)(p * r) * 0.04908738521234052f, &s, &c);   // 2*pi/128
        lut[r - 1][p] = make_float2(c, s);
    }

    float2 v[16];

    // ---- prologue fused with stage 1 (L=2048, R=16, stride 128) ----
    // V_k = e^{i*pi*k/8192}(x_k - i x_{4096-k});  V_0 = x_0 special.
    // Z_k = (V_k + V_{k+2048}) + i * e^{i*pi*k/2048} * (V_k - V_{k+2048}).
    float s0, c0;
    __sincosf((float)t * 3.8349519697141028e-4f, &s0, &c0);   // pi/8192
    const float2 e0 = make_float2(c0, s0);
    float2 f2 = cmul(e0, e0);
    float2 f4 = cmul(f2, f2);                                 // e^{i*pi*t/2048}
    float2 f8 = cmul(f4, f4);                                 // e^{2*pi*i*t/2048}

    // E_j = e^{i*pi*j/64}
    const float EC[16] = { 1.0f, 0.9987954562051724f, 0.9951847266721969f,
        0.9891765099647810f, 0.9807852804032304f, 0.9700312531945440f,
        0.9569403357322089f, 0.9415440651830208f, 0.9238795325112868f,
        0.9039892931234433f, 0.8819212643483551f, 0.8577286100002721f,
        0.8314696123025452f, 0.8032075314806449f, 0.7730104533627370f,
        0.7409511253549591f };
    const float ES[16] = { 0.0f, 0.0490676743274180f, 0.0980171403295606f,
        0.1467304744553618f, 0.1950903220161283f, 0.2429801799032639f,
        0.2902846772544624f, 0.3368898533922201f, 0.3826834323650898f,
        0.4275550934302821f, 0.4713967368259976f, 0.5141027441932217f,
        0.5555702330196022f, 0.5956993044924334f, 0.6343932841636455f,
        0.6715589548470183f };
    // G_j = e^{i*pi*j/16}
    const float GC[16] = { 1.0f,  0.9807852804032304f,  0.9238795325112868f,
        0.8314696123025452f,  0.7071067811865476f,  0.5555702330196022f,
        0.3826834323650898f,  0.1950903220161283f,  0.0f,
       -0.1950903220161283f, -0.3826834323650898f, -0.5555702330196022f,
       -0.7071067811865476f, -0.8314696123025452f, -0.9238795325112868f,
       -0.9807852804032304f };
    const float GS[16] = { 0.0f,  0.1950903220161283f,  0.3826834323650898f,
        0.5555702330196022f,  0.7071067811865476f,  0.8314696123025452f,
        0.9238795325112868f,  0.9807852804032304f,  1.0f,
        0.9807852804032304f,  0.9238795325112868f,  0.8314696123025452f,
        0.7071067811865476f,  0.5555702330196022f,  0.3826834323650898f,
        0.1950903220161283f };
    const float R2 = 0.7071067811865476f;

#pragma unroll
    for (int j = 0; j < 16; j++) {
        int   k  = t + 128 * j;                               // 0..2047
        float xa = __ldg(xr + k);
        float xb = __ldg(xr + ((N_FFT - k) & (N_FFT - 1)));
        float xc = __ldg(xr + (k + 2048));
        float xd = __ldg(xr + (2048 - k));
        // e_k = e0 * E_j = e^{i*pi*k/8192}
        float ekx = fmaf(e0.x, EC[j], -e0.y * ES[j]);
        float eky = fmaf(e0.x, ES[j],  e0.y * EC[j]);
        float v1x = fmaf(ekx, xa,  eky * xb);
        float v1y = fmaf(eky, xa, -ekx * xb);
        if (t == 0 && j == 0) { v1x = xa; v1y = 0.0f; }       // V_0 = x_0
        // V_{k+2048}: phase e_k * e^{i*pi/4}
        float c2x = R2 * (ekx - eky);
        float c2y = R2 * (ekx + eky);
        float v2x = fmaf(c2x, xc,  c2y * xd);
        float v2y = fmaf(c2y, xc, -c2x * xd);
        float Sx = v1x + v2x, Sy = v1y + v2y;
        float Dx = v1x - v2x, Dy = v1y - v2y;
        // e4k = e^{i*pi*k/2048} = f4 * G_j
        float e4x = fmaf(f4.x, GC[j], -f4.y * GS[j]);
        float e4y = fmaf(f4.x, GS[j],  f4.y * GC[j]);
        float edx = fmaf(e4x, Dx, -e4y * Dy);
        float edy = fmaf(e4x, Dy,  e4y * Dx);
        v[j] = make_float2(Sx - edy, Sy + edx);               // Z = S + i*(e4k*D)
    }
    dft16(v);
    twiddle16w(v, f8);                 // w1 = e^{2*pi*i*t/2048}
#pragma unroll
    for (int j = 0; j < 16; j++) buf[SWX(t + 128 * j)] = v[j];
    __syncthreads();

    // ---- stage 2 (L = 128, R = 16, stride 8), twiddles from LUT ----
    {
        const int B = (t >> 3) << 7, p = t & 7;
#pragma unroll
        for (int j = 0; j < 16; j++) v[j] = buf[SWX(B + p + 8 * j)];
        dft16(v);
#pragma unroll
        for (int r = 1; r < 16; r++) v[r] = cmul(v[r], lut[r - 1][p]);
#pragma unroll
        for (int r = 0; r < 16; r++) buf[SWX(B + p + 8 * r)] = v[r];
    }
    __syncthreads();

    // ---- fused stage 3 (radix-8, L = 8, no twiddles) + epilogue ----
    // slot s = 128 r1 + 8 r2 + p holds freq m = r1 + 16 r2 + 256 d after the
    // final length-8 DFT over q.  Octet g = 16 r1 + r2 yields w_{B+256d},
    // B = r1 + 16 r2.  Thread t owns B = t (gA = 16(t&15) + (t>>4)) and the
    // mirror B' = 255 - t (octet 255 - gA).
    float2 zA[8], zB[8], wA[8], wB[8];
    {
        const int gA = ((t & 15) << 4) + (t >> 4);
        const int gB = 255 - gA;
#pragma unroll
        for (int q = 0; q < 8; q++) zA[q] = buf[SWX(8 * gA + q)];
#pragma unroll
        for (int q = 0; q < 8; q++) zB[q] = buf[SWX(8 * gB + q)];
    }
    dft8(zA, wA);
    dft8(zB, wB);
    // wA[d] = w_{t+256d},  wB[d] = w_{255-t+256d}

    // y[4j..4j+3] = (Re w_j, Im w_{2047-j}, Im w_j, Re w_{2047-j}), j in [0,1024).
    // Thread t covers j = t+256d and j = 255-t+256d for d = 0..3:
    //   w_{2047-(t+256d)}     = w_{(255-t)+256(7-d)} = wB[7-d]
    //   w_{2047-(255-t+256d)} = w_{t+256(7-d)}       = wA[7-d]
    float4* o4 = (float4*)(y + rowoff);
#pragma unroll
    for (int d = 0; d < 4; d++) {
        o4[t + 256 * d]       = make_float4(wA[d].x, wB[7 - d].y,
                                            wA[d].y, wB[7 - d].x);
        o4[255 - t + 256 * d] = make_float4(wB[d].x, wA[7 - d].y,
                                            wB[d].y, wA[7 - d].x);
    }
}

extern "C" void kernel_launch(void* const* d_in, const int* in_sizes, int n_in,
                              void* d_out, int out_size) {
    (void)n_in; (void)out_size;
    const float* x = (const float*)d_in[0];
    float*       y = (float*)d_out;
    int rows = in_sizes[0] / N_FFT;      // 4096 for this problem
    idct_fft_kernel<<<rows, THREADS>>>(x, y);
}

// round 17
// speedup vs baseline: 1.0775x; 1.0775x over previous
#include <cuda_runtime.h>
#include <cstdint>

#define N_FFT   4096
#define THREADS 128

// XOR swizzle in float2-index space: bit1 ^= i8, bit2 ^= i9, bit3 ^= i7^i10.
// Bank-audited: stage-1 stores CF, stage-2 load/store CF, final octet gather 2-way.
__device__ __forceinline__ int SWX(int i) {
    return i ^ (((i >> 8) & 1) << 1) ^ (((i >> 9) & 1) << 2)
             ^ ((((i >> 7) ^ (i >> 10)) & 1) << 3);
}

__device__ __forceinline__ float2 cadd(float2 a, float2 b){ return make_float2(a.x+b.x, a.y+b.y); }
__device__ __forceinline__ float2 csub(float2 a, float2 b){ return make_float2(a.x-b.x, a.y-b.y); }
__device__ __forceinline__ float2 cmul(float2 a, float2 b){
    return make_float2(fmaf(a.x, b.x, -a.y*b.y), fmaf(a.x, b.y, a.y*b.x));
}
__device__ __forceinline__ float2 cmuli(float2 a){ return make_float2(-a.y, a.x); }   // *(+i)

// 8-point DFT core, omega8 = e^{+2*pi*i/8}  (positive-sign DFT)
__device__ __forceinline__ void dft8(const float2 a[8], float2 b[8]) {
    float2 t0 = cadd(a[0], a[4]);
    float2 t1 = csub(a[0], a[4]);
    float2 t2 = cadd(a[2], a[6]);
    float2 t3 = cmuli(csub(a[2], a[6]));
    float2 u0 = cadd(a[1], a[5]);
    float2 u1 = csub(a[1], a[5]);
    float2 u2 = cadd(a[3], a[7]);
    float2 u3 = cmuli(csub(a[3], a[7]));

    float2 E0 = cadd(t0, t2), E2 = csub(t0, t2);
    float2 E1 = cadd(t1, t3), E3 = csub(t1, t3);
    float2 O0 = cadd(u0, u2), O2 = csub(u0, u2);
    float2 O1 = cadd(u1, u3), O3 = csub(u1, u3);

    const float r = 0.7071067811865476f;
    float2 W1 = make_float2(r * (O1.x - O1.y),  r * (O1.x + O1.y));
    float2 W2 = cmuli(O2);
    float2 W3 = make_float2(-r * (O3.x + O3.y), r * (O3.x - O3.y));

    b[0] = cadd(E0, O0); b[4] = csub(E0, O0);
    b[1] = cadd(E1, W1); b[5] = csub(E1, W1);
    b[2] = cadd(E2, W2); b[6] = csub(E2, W2);
    b[3] = cadd(E3, W3); b[7] = csub(E3, W3);
}

// 16-point DFT (positive sign) via two dft8 + omega16^r combine. In place.
__device__ __forceinline__ void dft16(float2 v[16]) {
    float2 e[8], o[8], E[8], O[8];
#pragma unroll
    for (int n = 0; n < 8; n++) { e[n] = v[2*n]; o[n] = v[2*n+1]; }
    dft8(e, E);
    dft8(o, O);
    const float C = 0.9238795325112868f, S = 0.3826834323650898f, R = 0.7071067811865476f;
    float2 T[8];
    T[0] = O[0];
    T[1] = cmul(O[1], make_float2( C,  S));
    T[2] = make_float2(R*(O[2].x - O[2].y),  R*(O[2].x + O[2].y));   // *e^{i pi/4}
    T[3] = cmul(O[3], make_float2( S,  C));
    T[4] = cmuli(O[4]);
    T[5] = cmul(O[5], make_float2(-S,  C));
    T[6] = make_float2(-R*(O[6].x + O[6].y), R*(O[6].x - O[6].y));   // *e^{i 3pi/4}
    T[7] = cmul(O[7], make_float2(-C,  S));
#pragma unroll
    for (int r = 0; r < 8; r++) { v[r] = cadd(E[r], T[r]); v[r+8] = csub(E[r], T[r]); }
}

// v[r] *= w1^r, r=1..15, log-depth power generation.
__device__ __forceinline__ void twiddle16w(float2 v[16], float2 w1) {
    float2 w2  = cmul(w1, w1);   v[1]  = cmul(v[1],  w1);
    float2 w3  = cmul(w2, w1);   v[2]  = cmul(v[2],  w2);
    float2 w4  = cmul(w2, w2);   v[3]  = cmul(v[3],  w3);
    float2 w5  = cmul(w3, w2);   v[4]  = cmul(v[4],  w4);
    float2 w6  = cmul(w3, w3);   v[5]  = cmul(v[5],  w5);
    float2 w7  = cmul(w4, w3);   v[6]  = cmul(v[6],  w6);
    float2 w8  = cmul(w4, w4);   v[7]  = cmul(v[7],  w7);
    float2 w9  = cmul(w5, w4);   v[8]  = cmul(v[8],  w8);
    float2 w10 = cmul(w5, w5);   v[9]  = cmul(v[9],  w9);
    float2 w11 = cmul(w6, w5);   v[10] = cmul(v[10], w10);
    float2 w12 = cmul(w6, w6);   v[11] = cmul(v[11], w11);
    float2 w13 = cmul(w7, w6);   v[12] = cmul(v[12], w12);
    float2 w14 = cmul(w7, w7);   v[13] = cmul(v[13], w13);
    float2 w15 = cmul(w8, w7);   v[14] = cmul(v[14], w14);
                                 v[15] = cmul(v[15], w15);
}

// occ 6 (not 8): lifts the reg cap 64 -> ~85 so the 16-point state fits in
// registers instead of spilling to local (spills masqueraded as L1 traffic).
__global__ void __launch_bounds__(THREADS, 6)
idct_fft_kernel(const float* __restrict__ x, float* __restrict__ y) {
    __shared__ float2 buf[2048];       // exact: XOR swizzle is bijective, no padding
    __shared__ float2 lut[15][8];      // stage-2 twiddles e^{2*pi*i*p*r/128}, r=1..15
    const int t = threadIdx.x;
    const size_t rowoff = (size_t)blockIdx.x * N_FFT;
    const float* __restrict__ xr = x + rowoff;

    // ---- fill stage-2 twiddle LUT (ready after the first __syncthreads) ----
    if (t < 120) {
        int r = (t >> 3) + 1, p = t & 7;
        float s, c;
        __sincosf((float)(p * r) * 0.04908738521234052f, &s, &c);   // 2*pi/128
        lut[r - 1][p] = make_float2(c, s);
    }

    float2 v[16];

    // ---- prologue fused with stage 1 (L=2048, R=16, stride 128) ----
    // V_k = e^{i*pi*k/8192}(x_k - i x_{4096-k});  V_0 = x_0 special.
    // Z_k = (V_k + V_{k+2048}) + i * e^{i*pi*k/2048} * (V_k - V_{k+2048}).
    float s0, c0;
    __sincosf((float)t * 3.8349519697141028e-4f, &s0, &c0);   // pi/8192
    const float2 e0 = make_float2(c0, s0);
    float2 f2 = cmul(e0, e0);
    float2 f4 = cmul(f2, f2);                                 // e^{i*pi*t/2048}
    float2 f8 = cmul(f4, f4);                                 // e^{2*pi*i*t/2048}

    // E_j = e^{i*pi*j/64}
    const float EC[16] = { 1.0f, 0.9987954562051724f, 0.9951847266721969f,
        0.9891765099647810f, 0.9807852804032304f, 0.9700312531945440f,
        0.9569403357322089f, 0.9415440651830208f, 0.9238795325112868f,
        0.9039892931234433f, 0.8819212643483551f, 0.8577286100002721f,
        0.8314696123025452f, 0.8032075314806449f, 0.7730104533627370f,
        0.7409511253549591f };
    const float ES[16] = { 0.0f, 0.0490676743274180f, 0.0980171403295606f,
        0.1467304744553618f, 0.1950903220161283f, 0.2429801799032639f,
        0.2902846772544624f, 0.3368898533922201f, 0.3826834323650898f,
        0.4275550934302821f, 0.4713967368259976f, 0.5141027441932217f,
        0.5555702330196022f, 0.5956993044924334f, 0.6343932841636455f,
        0.6715589548470183f };
    // G_j = e^{i*pi*j/16}
    const float GC[16] = { 1.0f,  0.9807852804032304f,  0.9238795325112868f,
        0.8314696123025452f,  0.7071067811865476f,  0.5555702330196022f,
        0.3826834323650898f,  0.1950903220161283f,  0.0f,
       -0.1950903220161283f, -0.3826834323650898f, -0.5555702330196022f,
       -0.7071067811865476f, -0.8314696123025452f, -0.9238795325112868f,
       -0.9807852804032304f };
    const float GS[16] = { 0.0f,  0.1950903220161283f,  0.3826834323650898f,
        0.5555702330196022f,  0.7071067811865476f,  0.8314696123025452f,
        0.9238795325112868f,  0.9807852804032304f,  1.0f,
        0.9807852804032304f,  0.9238795325112868f,  0.8314696123025452f,
        0.7071067811865476f,  0.5555702330196022f,  0.3826834323650898f,
        0.1950903220161283f };
    const float R2 = 0.7071067811865476f;

#pragma unroll
    for (int j = 0; j < 16; j++) {
        int   k  = t + 128 * j;                               // 0..2047
        float xa = __ldg(xr + k);
        float xb = __ldg(xr + ((N_FFT - k) & (N_FFT - 1)));
        float xc = __ldg(xr + (k + 2048));
        float xd = __ldg(xr + (2048 - k));
        // e_k = e0 * E_j = e^{i*pi*k/8192}
        float ekx = fmaf(e0.x, EC[j], -e0.y * ES[j]);
        float eky = fmaf(e0.x, ES[j],  e0.y * EC[j]);
        float v1x = fmaf(ekx, xa,  eky * xb);
        float v1y = fmaf(eky, xa, -ekx * xb);
        if (t == 0 && j == 0) { v1x = xa; v1y = 0.0f; }       // V_0 = x_0
        // V_{k+2048}: phase e_k * e^{i*pi/4}
        float c2x = R2 * (ekx - eky);
        float c2y = R2 * (ekx + eky);
        float v2x = fmaf(c2x, xc,  c2y * xd);
        float v2y = fmaf(c2y, xc, -c2x * xd);
        float Sx = v1x + v2x, Sy = v1y + v2y;
        float Dx = v1x - v2x, Dy = v1y - v2y;
        // e4k = e^{i*pi*k/2048} = f4 * G_j
        float e4x = fmaf(f4.x, GC[j], -f4.y * GS[j]);
        float e4y = fmaf(f4.x, GS[j],  f4.y * GC[j]);
        float edx = fmaf(e4x, Dx, -e4y * Dy);
        float edy = fmaf(e4x, Dy,  e4y * Dx);
        v[j] = make_float2(Sx - edy, Sy + edx);               // Z = S + i*(e4k*D)
    }
    dft16(v);
    twiddle16w(v, f8);                 // w1 = e^{2*pi*i*t/2048}
#pragma unroll
    for (int j = 0; j < 16; j++) buf[SWX(t + 128 * j)] = v[j];
    __syncthreads();

    // ---- stage 2 (L = 128, R = 16, stride 8), twiddles from LUT ----
    {
        const int B = (t >> 3) << 7, p = t & 7;
#pragma unroll
        for (int j = 0; j < 16; j++) v[j] = buf[SWX(B + p + 8 * j)];
        dft16(v);
#pragma unroll
        for (int r = 1; r < 16; r++) v[r] = cmul(v[r], lut[r - 1][p]);
#pragma unroll
        for (int r = 0; r < 16; r++) buf[SWX(B + p + 8 * r)] = v[r];
    }
    __syncthreads();

    // ---- fused stage 3 (radix-8, L = 8, no twiddles) + epilogue ----
    // Octet g = 16 r1 + r2 yields w_{B+256d}, B = r1 + 16 r2.  Thread t owns
    // B = t (gA = 16(t&15) + (t>>4)) and mirror B' = 255 - t (octet 255-gA).
    // Scoped so zB loads start only after wA is finalized (halves live set).
    float2 wA[8], wB[8];
    const int gA = ((t & 15) << 4) + (t >> 4);
    {
        float2 zA[8];
#pragma unroll
        for (int q = 0; q < 8; q++) zA[q] = buf[SWX(8 * gA + q)];
        dft8(zA, wA);                  // wA[d] = w_{t+256d}
    }
    {
        float2 zB[8];
        const int gB = 255 - gA;
#pragma unroll
        for (int q = 0; q < 8; q++) zB[q] = buf[SWX(8 * gB + q)];
        dft8(zB, wB);                  // wB[d] = w_{255-t+256d}
    }

    // y[4j..4j+3] = (Re w_j, Im w_{2047-j}, Im w_j, Re w_{2047-j}), j in [0,1024).
    // Thread t covers j = t+256d and j = 255-t+256d for d = 0..3:
    //   w_{2047-(t+256d)}     = wB[7-d],   w_{2047-(255-t+256d)} = wA[7-d]
    float4* o4 = (float4*)(y + rowoff);
#pragma unroll
    for (int d = 0; d < 4; d++) {
        o4[t + 256 * d]       = make_float4(wA[d].x, wB[7 - d].y,
                                            wA[d].y, wB[7 - d].x);
        o4[255 - t + 256 * d] = make_float4(wB[d].x, wA[7 - d].y,
                                            wB[d].y, wA[7 - d].x);
    }
}

extern "C" void kernel_launch(void* const* d_in, const int* in_sizes, int n_in,
                              void* d_out, int out_size) {
    (void)n_in; (void)out_size;
    const float* x = (const float*)d_in[0];
    float*       y = (float*)d_out;
    int rows = in_sizes[0] / N_FFT;      // 4096 for this problem
    idct_fft_kernel<<<rows, THREADS>>>(x, y);
}